// round 17
// baseline (speedup 1.0000x reference)
#include <cuda_runtime.h>
#include <cuda_fp16.h>
#include <math.h>
#include <stdint.h>

#define EPSF 1e-8f
#define MARGINF 0.2f
#define NATT 1280

typedef __half fp16;

__device__ __forceinline__ uint32_t h2u(__half2 h) {
    return *reinterpret_cast<uint32_t*>(&h);
}

// ======================= scratch (no allocation; zero-initialized) =======================
__device__ fp16 g_vidh[4194304], g_vidl[4194304];       // video split A (1024x4096)
__device__ fp16 g_wt0h[4194304];                        // conv0 weight T (B)
__device__ fp16 g_wt1h[4194304];                        // conv1 weight T
__device__ fp16 g_wt2h[4194304];                        // conv2 weight T
__device__ fp16 g_vh[1572864],   g_vl[1572864];         // conv outputs split A (rows 1344+ stay 0)
__device__ fp16 g_uh[1572864],   g_ul[1572864];         // u split A (rows 1344+ stay 0)
__device__ fp16 g_wdh[1310720];                         // words (B)
__device__ fp16 g_cdh[1048576];                         // conv1d w (B)
__device__ fp16 g_fch[1048576];                         // fc w (B)
__device__ fp16 g_sth[131072],   g_stl[131072];         // sentences split A + pad (128x1024)
__device__ fp16 g_gph[131072];                          // gpre (B; rows 64+ stay 0)
__device__ float g_part[4194304];                       // split-K partials
__device__ float g_att[1720320];                        // attention logits (1344x1280)
__device__ float g_gsraw[16384];                        // 128x128 (top 64x64 valid)
__device__ float g_sall[64 * 64 * 21];
__device__ float g_sc[4096];
__device__ float g_G[64 * 400];
__device__ float g_un[1344];
__device__ float g_sn[64];
__device__ float g_gn[64];

#define CONV1D_SLICE 1572864
#define ATT_SLICE    1966080
#define GS_OFF       3932160

// ======================= mega-prep: all input splits + weightT + sent norm + gram ========
__device__ __forceinline__ void pack8(const float4& v0, const float4& v1,
                                      uint4& ho, uint4& lo_) {
    __half2 h0 = __floats2half2_rn(v0.x, v0.y);
    __half2 h1 = __floats2half2_rn(v0.z, v0.w);
    __half2 h2 = __floats2half2_rn(v1.x, v1.y);
    __half2 h3 = __floats2half2_rn(v1.z, v1.w);
    ho.x = h2u(h0); ho.y = h2u(h1); ho.z = h2u(h2); ho.w = h2u(h3);
    __half2 l0 = __floats2half2_rn(v0.x - __low2float(h0),  v0.y - __high2float(h0));
    __half2 l1 = __floats2half2_rn(v0.z - __low2float(h1),  v0.w - __high2float(h1));
    __half2 l2 = __floats2half2_rn(v1.x - __low2float(h2),  v1.y - __high2float(h2));
    __half2 l3 = __floats2half2_rn(v1.z - __low2float(h3),  v1.w - __high2float(h3));
    lo_.x = h2u(l0); lo_.y = h2u(l1); lo_.z = h2u(l2); lo_.w = h2u(l3);
}
__device__ __forceinline__ void split8A(const float* __restrict__ x, fp16* __restrict__ hi,
                                        fp16* __restrict__ lo, int idx, int n) {
    int i8 = idx * 8;
    float4 v0 = {0, 0, 0, 0}, v1 = {0, 0, 0, 0};
    if (i8 < n) { v0 = *(const float4*)(x + i8); v1 = *(const float4*)(x + i8 + 4); }
    uint4 ho, lw;
    pack8(v0, v1, ho, lw);
    *(uint4*)(hi + i8) = ho;
    *(uint4*)(lo + i8) = lw;
}
__device__ __forceinline__ void split8B(const float* __restrict__ x, fp16* __restrict__ hi,
                                        int idx, int n) {
    int i8 = idx * 8;
    float4 v0 = {0, 0, 0, 0}, v1 = {0, 0, 0, 0};
    if (i8 < n) { v0 = *(const float4*)(x + i8); v1 = *(const float4*)(x + i8 + 4); }
    uint4 ho;
    ho.x = h2u(__floats2half2_rn(v0.x, v0.y));
    ho.y = h2u(__floats2half2_rn(v0.z, v0.w));
    ho.z = h2u(__floats2half2_rn(v1.x, v1.y));
    ho.w = h2u(__floats2half2_rn(v1.z, v1.w));
    *(uint4*)(hi + i8) = ho;
}
__global__ void prep_k(const float* __restrict__ video, fp16* __restrict__ vidh, fp16* __restrict__ vidl,
                       const float* __restrict__ words, fp16* __restrict__ wdh,
                       const float* __restrict__ sent, fp16* __restrict__ sth, fp16* __restrict__ stl,
                       const float* __restrict__ cdw, fp16* __restrict__ cdh,
                       const float* __restrict__ fcw, fp16* __restrict__ fch,
                       const float* __restrict__ w0, fp16* __restrict__ wt0,
                       const float* __restrict__ w1, fp16* __restrict__ wt1,
                       const float* __restrict__ w2, fp16* __restrict__ wt2,
                       float* __restrict__ sn, float* __restrict__ G) {
    __shared__ float ws[4224];
    int b = blockIdx.x, tid = threadIdx.x;
    if (b < 2048)      { split8A(video, vidh, vidl, b * 256 + tid, 4194304); return; }
    if (b < 2688)      { split8B(words, wdh, (b - 2048) * 256 + tid, 1310720); return; }
    if (b < 2752)      { split8A(sent, sth, stl, (b - 2688) * 256 + tid, 65536); return; }
    if (b < 3264)      { split8B(cdw, cdh, (b - 2752) * 256 + tid, 1048576); return; }
    if (b < 3776)      { split8B(fcw, fch, (b - 3264) * 256 + tid, 1048576); return; }
    if (b < 6848) {
        int x = b - 3776, cv = x >> 10, o = x & 1023;
        const float* w = (cv == 0) ? w0 : (cv == 1) ? w1 : w2;
        fp16* hi = (cv == 0) ? wt0 : (cv == 1) ? wt1 : wt2;
        const float* wo = w + (size_t)o * 4096;
        for (int q = tid; q < 4096; q += 256) ws[q + (q >> 5)] = wo[q];
        __syncthreads();
        for (int q = tid; q < 4096; q += 256) {
            int k = q >> 10, i = q & 1023;
            int a = i * 4 + k;
            hi[(size_t)o * 4096 + q] = __float2half(ws[a + (a >> 5)]);
        }
        return;
    }
    if (b < 6912) {     // rownorm of sentences
        int r = b - 6848;
        const float* x = sent + (size_t)r * 1024;
        float s = 0.f;
        for (int k = tid; k < 1024; k += 256) { float v = x[k]; s += v * v; }
        ws[tid] = s; __syncthreads();
        for (int off = 128; off > 0; off >>= 1) {
            if (tid < off) ws[tid] += ws[tid + off];
            __syncthreads();
        }
        if (tid == 0) sn[r] = fmaxf(sqrtf(ws[0]), EPSF);
        return;
    }
    {                   // gram
        int i = b - 6912;
        int warp = tid >> 5, lane = tid & 31;
        const float4* base = (const float4*)(words + (size_t)i * 20480);
        for (int p = warp; p < 400; p += 8) {
            int w = p / 20, w2 = p % 20;
            const float4* x = base + w * 256;
            const float4* y = base + w2 * 256;
            float s = 0.f;
#pragma unroll
            for (int k = lane; k < 256; k += 32) {
                float4 a = x[k], bb = y[k];
                s += a.x * bb.x + a.y * bb.y + a.z * bb.z + a.w * bb.w;
            }
            for (int off = 16; off; off >>= 1) s += __shfl_down_sync(0xffffffffu, s, off);
            if (lane == 0) G[i * 400 + p] = s;
        }
    }
}

// ======================= mma.sync / cp.async helpers =======================
__device__ __forceinline__ uint32_t s2u(const void* p) {
    uint32_t a;
    asm("{ .reg .u64 t; cvta.to.shared.u64 t, %1; cvt.u32.u64 %0, t; }" : "=r"(a) : "l"(p));
    return a;
}
__device__ __forceinline__ void ldm4(uint32_t* r, uint32_t addr) {
    asm volatile("ldmatrix.sync.aligned.m8n8.x4.shared.b16 {%0,%1,%2,%3}, [%4];"
                 : "=r"(r[0]), "=r"(r[1]), "=r"(r[2]), "=r"(r[3]) : "r"(addr));
}
__device__ __forceinline__ void mma_fp16(float* c, const uint32_t* a, const uint32_t* b) {
    asm volatile("mma.sync.aligned.m16n8k16.row.col.f32.f16.f16.f32 "
                 "{%0,%1,%2,%3}, {%4,%5,%6,%7}, {%8,%9}, {%0,%1,%2,%3};"
                 : "+f"(c[0]), "+f"(c[1]), "+f"(c[2]), "+f"(c[3])
                 : "r"(a[0]), "r"(a[1]), "r"(a[2]), "r"(a[3]), "r"(b[0]), "r"(b[1]));
}
__device__ __forceinline__ void cp64(uint32_t s, const char* g) {
#pragma unroll
    for (int q = 0; q < 4; q++)
        asm volatile("cp.async.cg.shared.global [%0], [%1], 16;"
                     :: "r"(s + q * 16), "l"(g + q * 16));
}
#define CP_COMMIT() asm volatile("cp.async.commit_group;" ::: "memory")
#define CP_WAIT(n)  asm volatile("cp.async.wait_group %0;" :: "n"(n) : "memory")

// ======================= fp16x2 HMMA split-K GEMM, BK=64 =======================
// C = (Ah+Al) * Bh. TM x 128 tile, BK=64 (pitch 144B), 512 threads, ST-stage cp.async,
// one barrier per 64-K chunk. Alt path for folded second GEMM (blockIdx.y >= ySplit).
template<int TM, int ST>
__global__ void __launch_bounds__(512)
gemm_sk(const fp16* __restrict__ Ah_, const fp16* __restrict__ Al_,
        const fp16* __restrict__ Bh_,
        float* __restrict__ P, int N, int K, int Ks,
        const fp16* A2h, const fp16* A2l, const fp16* B2h,
        float* P2, int N2, int stride2, int ySplit) {
    constexpr int WM = TM / 32;          // 8 or 4
    constexpr int WN = 16 / WM;          // 2 or 4
    constexpr int NT = 16 / WN;          // 8 or 4
    constexpr uint32_t PIT = 144u;
    constexpr uint32_t SA = (uint32_t)TM * PIT;
    constexpr uint32_t SB = 128u * PIT;
    constexpr uint32_t STG = 2u * SA + SB;

    const bool alt = ((int)blockIdx.y >= ySplit);
    if (alt && ((int)blockIdx.x << 7) >= N2) return;

    extern __shared__ char smem[];
    const uint32_t sbase = s2u(smem);
    const int tid = threadIdx.x, lane = tid & 31, wid = tid >> 5;
    const int warp_m = wid % WM, warp_n = wid / WM;
    const int bn = blockIdx.x << 7;
    const int sl = blockIdx.z;
    const int bm = alt ? 0 : blockIdx.y * TM;
    const int Nn = alt ? N2 : N;
    const fp16* __restrict__ Ah = alt ? A2h : Ah_;
    const fp16* __restrict__ Al = alt ? A2l : Al_;
    const fp16* __restrict__ Bh = alt ? B2h : Bh_;
    float* Pout = alt ? (P2 + (size_t)sl * stride2)
                      : (P + (size_t)sl * ((size_t)gridDim.y * TM) * N);

    const size_t K2 = (size_t)K * 2;
    const size_t k0b = (size_t)sl * Ks * 2;
    const uint32_t coloff = (uint32_t)(tid & 1) * 64u;
    const bool doB = (tid < 256);

    const char *pA0, *pA1 = nullptr, *pB = nullptr;
    uint32_t sA0, sA1 = 0, sBo = 0;
    if (TM == 256) {
        int arow = tid >> 1;
        pA0 = (const char*)Ah + (size_t)(bm + arow) * K2 + coloff + k0b;
        sA0 = arow * PIT + coloff;
        pA1 = (const char*)Al + (size_t)(bm + arow) * K2 + coloff + k0b;
        sA1 = SA + arow * PIT + coloff;
        if (doB) {
            int brow = tid >> 1;
            pB = (const char*)Bh + (size_t)(bn + brow) * K2 + coloff + k0b;
            sBo = 2u * SA + brow * PIT + coloff;
        }
    } else {
        int arow = (tid >> 1) & 127;
        pA0 = (const char*)(tid < 256 ? Ah : Al) + (size_t)(bm + arow) * K2 + coloff + k0b;
        sA0 = (tid < 256 ? 0u : SA) + arow * PIT + coloff;
        if (doB) {
            int brow = tid >> 1;
            pB = (const char*)Bh + (size_t)(bn + brow) * K2 + coloff + k0b;
            sBo = 2u * SA + brow * PIT + coloff;
        }
    }

    const uint32_t a_off = (uint32_t)((warp_m * 32 + (lane & 15)) * PIT + (lane & 16));
    const uint32_t b_row = (uint32_t)(warp_n * (NT * 8) + (lane & 7) + ((lane & 16) ? 8 : 0));
    const uint32_t b_off = 2u * SA + b_row * PIT + ((lane & 8) ? 16u : 0u);

    float acc[2][NT][4];
#pragma unroll
    for (int mt = 0; mt < 2; mt++)
#pragma unroll
        for (int nt = 0; nt < NT; nt++)
#pragma unroll
            for (int q = 0; q < 4; q++) acc[mt][nt][q] = 0.f;

    const int nch = Ks >> 6;
#pragma unroll
    for (int s = 0; s < ST - 1; s++) {
        const uint32_t sb = sbase + (uint32_t)s * STG;
        const size_t koff = (size_t)s * 128;
        cp64(sb + sA0, pA0 + koff);
        if (TM == 256) cp64(sb + sA1, pA1 + koff);
        if (doB) cp64(sb + sBo, pB + koff);
        CP_COMMIT();
    }

    for (int c = 0; c < nch; c++) {
        if (ST == 2) { CP_WAIT(0); }
        else { if (c + 1 < nch) { CP_WAIT(1); } else { CP_WAIT(0); } }
        __syncthreads();
        if (c + ST - 1 < nch) {
            const size_t koff = (size_t)(c + ST - 1) * 128;
            const uint32_t sb = sbase + (uint32_t)((c + ST - 1) % ST) * STG;
            cp64(sb + sA0, pA0 + koff);
            if (TM == 256) cp64(sb + sA1, pA1 + koff);
            if (doB) cp64(sb + sBo, pB + koff);
            CP_COMMIT();
        }
        const uint32_t buf = sbase + (uint32_t)(c % ST) * STG;
#pragma unroll
        for (int ks = 0; ks < 4; ks++) {
            const uint32_t kb = (uint32_t)ks * 32u;
            uint32_t aH[2][4], aL[2][4], bT[NT][2];
#pragma unroll
            for (int mt = 0; mt < 2; mt++) {
                ldm4(aH[mt], buf + a_off + (uint32_t)(mt * 16) * PIT + kb);
                ldm4(aL[mt], buf + SA + a_off + (uint32_t)(mt * 16) * PIT + kb);
            }
#pragma unroll
            for (int g = 0; g < NT / 2; g++)
                ldm4(&bT[g * 2][0], buf + b_off + (uint32_t)(g * 16) * PIT + kb);
#pragma unroll
            for (int mt = 0; mt < 2; mt++)
#pragma unroll
                for (int nt = 0; nt < NT; nt++)
                    mma_fp16(acc[mt][nt], aH[mt], bT[nt]);
#pragma unroll
            for (int mt = 0; mt < 2; mt++)
#pragma unroll
                for (int nt = 0; nt < NT; nt++)
                    mma_fp16(acc[mt][nt], aL[mt], bT[nt]);
        }
    }

    const int r0 = (alt ? 0 : bm) + warp_m * 32 + (lane >> 2);
    const int c0 = bn + warp_n * (NT * 8) + (lane & 3) * 2;
#pragma unroll
    for (int mt = 0; mt < 2; mt++) {
#pragma unroll
        for (int nt = 0; nt < NT; nt++) {
            int col = c0 + nt * 8;
            float2 u0, u1;
            u0.x = acc[mt][nt][0]; u0.y = acc[mt][nt][1];
            u1.x = acc[mt][nt][2]; u1.y = acc[mt][nt][3];
            *(float2*)(Pout + (size_t)(r0 + mt * 16) * Nn + col) = u0;
            *(float2*)(Pout + (size_t)(r0 + mt * 16 + 8) * Nn + col) = u1;
        }
    }
}

// ======================= vectorized finish (4 elems/thread) =======================
template<bool RELU, bool BIAS>
__global__ void finish_k(const float* __restrict__ P, int S, int MNused, int MNfull,
                         const float* __restrict__ bias,
                         float* __restrict__ f32o,
                         fp16* __restrict__ hi, fp16* __restrict__ lo) {
    int i4 = (blockIdx.x * blockDim.x + threadIdx.x) * 4;
    if (i4 >= MNused) return;
    float4 a = *(const float4*)(P + i4);
    for (int s = 1; s < S; s++) {
        float4 b = *(const float4*)(P + (size_t)s * MNfull + i4);
        a.x += b.x; a.y += b.y; a.z += b.z; a.w += b.w;
    }
    if (BIAS) {
        float4 b = *(const float4*)(bias + (i4 & 1023));
        a.x += b.x; a.y += b.y; a.z += b.z; a.w += b.w;
    }
    if (RELU) {
        a.x = fmaxf(a.x, 0.f); a.y = fmaxf(a.y, 0.f);
        a.z = fmaxf(a.z, 0.f); a.w = fmaxf(a.w, 0.f);
    }
    if (f32o) *(float4*)(f32o + i4) = a;
    if (hi) {
        __half2 h0 = __floats2half2_rn(a.x, a.y);
        __half2 h1 = __floats2half2_rn(a.z, a.w);
        uint2 ho = {h2u(h0), h2u(h1)};
        *(uint2*)(hi + i4) = ho;
        __half2 l0 = __floats2half2_rn(a.x - __low2float(h0), a.y - __high2float(h0));
        __half2 l1 = __floats2half2_rn(a.z - __low2float(h1), a.w - __high2float(h1));
        uint2 lw = {h2u(l0), h2u(l1)};
        *(uint2*)(lo + i4) = lw;
    }
}

// merged finish for att (S=2) + gsraw (S=2)
__global__ void finish2_k(const float* __restrict__ P, float* __restrict__ att,
                          float* __restrict__ gsraw) {
    int b = blockIdx.x;
    if (b < 1680) {
        int i4 = (b * 256 + threadIdx.x) * 4;
        if (i4 >= 1720320) return;
        float4 a = *(const float4*)(P + i4);
        float4 c = *(const float4*)(P + (size_t)ATT_SLICE + i4);
        a.x += c.x; a.y += c.y; a.z += c.z; a.w += c.w;
        *(float4*)(att + i4) = a;
    } else {
        int i4 = ((b - 1680) * 256 + threadIdx.x) * 4;
        if (i4 >= 16384) return;
        const float* p = P + GS_OFF;
        float4 a = *(const float4*)(p + i4);
        float4 c = *(const float4*)(p + 16384 + i4);
        a.x += c.x; a.y += c.y; a.z += c.z; a.w += c.w;
        *(float4*)(gsraw + i4) = a;
    }
}

// merged finishrow: conv1d rows -> uh/ul/un ; fc rows -> gph + gn. S=2, vectorized.
__global__ void finishrow2_k(const float* __restrict__ P,
                             const float* __restrict__ cdb, const float* __restrict__ fcb,
                             fp16* __restrict__ uh, fp16* __restrict__ ul, float* __restrict__ un,
                             fp16* __restrict__ gph, float* __restrict__ gn) {
    int r = blockIdx.x;   // 0..1407
    int pr, orow;
    const float* bias;
    fp16 *oh, *ol;
    float* on;
    if (r < 1344) { pr = r; bias = cdb; oh = uh; ol = ul; on = un; orow = r; }
    else { int rf = r - 1344; pr = 1408 + rf; bias = fcb; oh = gph; ol = nullptr; on = gn; orow = rf; }
    const float* p = P + (size_t)pr * 1024;
    int k4 = threadIdx.x * 4;
    float4 a = *(const float4*)(p + k4);
    float4 b = *(const float4*)(p + CONV1D_SLICE + k4);
    float4 bv = *(const float4*)(bias + k4);
    a.x += b.x + bv.x; a.y += b.y + bv.y; a.z += b.z + bv.z; a.w += b.w + bv.w;
    __half2 h0 = __floats2half2_rn(a.x, a.y);
    __half2 h1 = __floats2half2_rn(a.z, a.w);
    uint2 ho = {h2u(h0), h2u(h1)};
    *(uint2*)(oh + (size_t)orow * 1024 + k4) = ho;
    if (ol) {
        __half2 l0 = __floats2half2_rn(a.x - __low2float(h0), a.y - __high2float(h0));
        __half2 l1 = __floats2half2_rn(a.z - __low2float(h1), a.w - __high2float(h1));
        uint2 lw = {h2u(l0), h2u(l1)};
        *(uint2*)(ol + (size_t)orow * 1024 + k4) = lw;
    }
    float sq = a.x * a.x + a.y * a.y + a.z * a.z + a.w * a.w;
    __shared__ float red[256];
    red[threadIdx.x] = sq; __syncthreads();
    for (int off = 128; off > 0; off >>= 1) {
        if (threadIdx.x < off) red[threadIdx.x] += red[threadIdx.x + off];
        __syncthreads();
    }
    if (threadIdx.x == 0) on[orow] = fmaxf(sqrtf(red[0]), EPSF);
}

// ======================= epilogue kernels =======================
__global__ void __launch_bounds__(192)
sim_k(const float* __restrict__ att, const float* __restrict__ G,
      const float* __restrict__ un, const int* __restrict__ wmask,
      float* __restrict__ sall) {
    int i = blockIdx.x / 7, seg = blockIdx.x % 7;
    __shared__ float Gs[400];
    __shared__ float mk[20];
    for (int p = threadIdx.x; p < 400; p += 192) Gs[p] = G[i * 400 + p];
    if (threadIdx.x < 20)
        mk[threadIdx.x] = (wmask[i * 20 + threadIdx.x] > 0) ? 0.f : -1e30f;
    __syncthreads();
    int item = seg * 192 + threadIdx.x;
    int j = item / 21, t = item % 21;
    int r;
    if (t < 16)       r = j * 16 + t;
    else if (t < 20)  r = 1024 + j * 4 + (t - 16);
    else              r = 1280 + j;
    const float* arow = att + (size_t)r * NATT + i * 20;
    float a[20], am[20], e[20];
    float m = -1e38f;
#pragma unroll
    for (int w = 0; w < 20; w++) { a[w] = arow[w]; am[w] = a[w] + mk[w]; m = fmaxf(m, am[w]); }
    float s = 0.f;
#pragma unroll
    for (int w = 0; w < 20; w++) { e[w] = __expf(am[w] - m); s += e[w]; }
    float inv = 1.f / s;
    float num = 0.f;
#pragma unroll
    for (int w = 0; w < 20; w++) { e[w] *= inv; num += e[w] * a[w]; }
    float den2 = 0.f;
#pragma unroll
    for (int w = 0; w < 20; w++) {
        float q = 0.f;
#pragma unroll
        for (int w2 = 0; w2 < 20; w2++) q += e[w2] * Gs[w * 20 + w2];
        den2 += e[w] * q;
    }
    float sim = num / (un[r] * fmaxf(sqrtf(den2), EPSF));
    sall[((size_t)i * 64 + j) * 21 + t] = sim;
}

__global__ void scores_k(const float* __restrict__ sall, float* __restrict__ sc,
                         float* __restrict__ out) {
    int idx = blockIdx.x * blockDim.x + threadIdx.x;
    if (idx >= 4096) return;
    const float* p = sall + (size_t)idx * 21;
    float s = 0.f;
#pragma unroll
    for (int t = 0; t < 21; t++) s += p[t];
    sc[idx] = s * (1.f / 21.f);
    int i = idx >> 6, j = idx & 63;
    if (i == j) {
#pragma unroll
        for (int t = 0; t < 21; t++) out[1 + i * 21 + t] = p[t];
    }
}

__global__ void loss_k(const float* __restrict__ sc, const float* __restrict__ gs,
                       const float* __restrict__ sn, const float* __restrict__ gn,
                       float* __restrict__ out) {
    __shared__ float ds[64], dg[64], isn[64], ign[64];
    int tid = threadIdx.x;
    if (tid < 64) {
        ds[tid] = sc[tid * 65];
        isn[tid] = 1.f / sn[tid];
        ign[tid] = 1.f / gn[tid];
        dg[tid] = gs[tid * 129] * (1.f / (sn[tid] * gn[tid]));
    }
    __syncthreads();
    float acc = 0.f;
    for (int idx = tid; idx < 4096; idx += blockDim.x) {
        int i = idx >> 6, j = idx & 63;
        if (i == j) continue;
        float s = sc[idx];
        acc += fmaxf(MARGINF + s - ds[i], 0.f) + fmaxf(MARGINF + s - ds[j], 0.f);
        float g = gs[i * 128 + j] * isn[i] * ign[j];
        acc += fmaxf(MARGINF + g - dg[i], 0.f) + fmaxf(MARGINF + g - dg[j], 0.f);
    }
    __shared__ float red[256];
    red[tid] = acc; __syncthreads();
    for (int off = 128; off; off >>= 1) {
        if (tid < off) red[tid] += red[tid + off];
        __syncthreads();
    }
    if (tid == 0) out[0] = red[0] * (1.f / 64.f);
}

// ======================= launch =======================
#define SMEM256 184320
#define SMEM128 165888

extern "C" void kernel_launch(void* const* d_in, const int* in_sizes, int n_in,
                              void* d_out, int out_size) {
    const float* video = (const float*)d_in[0];
    const float* words = (const float*)d_in[1];
    const int*   wmask = (const int*)d_in[2];
    const float* sent  = (const float*)d_in[3];
    const float* c0w = (const float*)d_in[4];  const float* c0b = (const float*)d_in[5];
    const float* c1w = (const float*)d_in[6];  const float* c1b = (const float*)d_in[7];
    const float* c2w = (const float*)d_in[8];  const float* c2b = (const float*)d_in[9];
    const float* cdw = (const float*)d_in[10]; const float* cdb = (const float*)d_in[11];
    const float* fcw = (const float*)d_in[12]; const float* fcb = (const float*)d_in[13];
    float* out = (float*)d_out;
    (void)in_sizes; (void)n_in; (void)out_size;

    cudaFuncSetAttribute(gemm_sk<256, 2>, cudaFuncAttributeMaxDynamicSharedMemorySize, SMEM256);
    cudaFuncSetAttribute(gemm_sk<128, 3>, cudaFuncAttributeMaxDynamicSharedMemorySize, SMEM128);

    fp16 *vidh, *vidl, *wt0h, *wt1h, *wt2h, *vh, *vl;
    fp16 *uh, *ul, *wdh, *cdh, *fch, *sth, *stl, *gph;
    float *part, *att, *gsraw, *sall, *sc, *G, *un, *sn, *gn;
    cudaGetSymbolAddress((void**)&vidh, g_vidh); cudaGetSymbolAddress((void**)&vidl, g_vidl);
    cudaGetSymbolAddress((void**)&wt0h, g_wt0h);
    cudaGetSymbolAddress((void**)&wt1h, g_wt1h);
    cudaGetSymbolAddress((void**)&wt2h, g_wt2h);
    cudaGetSymbolAddress((void**)&vh, g_vh);     cudaGetSymbolAddress((void**)&vl, g_vl);
    cudaGetSymbolAddress((void**)&uh, g_uh);     cudaGetSymbolAddress((void**)&ul, g_ul);
    cudaGetSymbolAddress((void**)&wdh, g_wdh);
    cudaGetSymbolAddress((void**)&cdh, g_cdh);
    cudaGetSymbolAddress((void**)&fch, g_fch);
    cudaGetSymbolAddress((void**)&sth, g_sth);   cudaGetSymbolAddress((void**)&stl, g_stl);
    cudaGetSymbolAddress((void**)&gph, g_gph);
    cudaGetSymbolAddress((void**)&part, g_part);
    cudaGetSymbolAddress((void**)&att, g_att);
    cudaGetSymbolAddress((void**)&gsraw, g_gsraw);
    cudaGetSymbolAddress((void**)&sall, g_sall); cudaGetSymbolAddress((void**)&sc, g_sc);
    cudaGetSymbolAddress((void**)&G, g_G);       cudaGetSymbolAddress((void**)&un, g_un);
    cudaGetSymbolAddress((void**)&sn, g_sn);     cudaGetSymbolAddress((void**)&gn, g_gn);

    // 1: all independent prep in one launch
    prep_k<<<6976, 256>>>(video, vidh, vidl, words, wdh, sent, sth, stl,
                          cdw, cdh, fcw, fch,
                          c0w, wt0h, c1w, wt1h, c2w, wt2h, sn, G);

    // 2: conv0 GEMM: M=1024 N=1024 K=4096, S=4 Ks=1024 (128 CTAs, nch=16)
    gemm_sk<256, 2><<<dim3(8, 4, 4), 512, SMEM256>>>(vidh, vidl, wt0h, part, 1024, 4096, 1024,
        nullptr, nullptr, nullptr, nullptr, 0, 0, 1 << 20);
    finish_k<true, true><<<1024, 256>>>(part, 4, 1048576, 1048576, c0b, nullptr, vh, vl);

    // conv1: M=256 N=1024 K=4096, S=16 Ks=256 (128 CTAs, nch=4)
    gemm_sk<256, 2><<<dim3(8, 1, 16), 512, SMEM256>>>(vh, vl, wt1h, part, 1024, 4096, 256,
        nullptr, nullptr, nullptr, nullptr, 0, 0, 1 << 20);
    finish_k<true, true><<<256, 256>>>(part, 16, 262144, 262144, c1b, nullptr,
                                       vh + 1048576, vl + 1048576);

    // conv2: A = direct 64x4096 re-view of v2 rows (pad rows read valid data, never finished)
    gemm_sk<128, 3><<<dim3(8, 1, 16), 512, SMEM128>>>(vh + 1048576, vl + 1048576, wt2h,
        part, 1024, 4096, 256,
        nullptr, nullptr, nullptr, nullptr, 0, 0, 1 << 20);
    finish_k<true, true><<<64, 256>>>(part, 16, 65536, 131072, c2b, nullptr,
                                      vh + 1310720, vl + 1310720);

    // conv1d (+ fc folded as y=11): N=1024, K=1024, S=2 Ks=512 (192 CTAs, nch=8)
    gemm_sk<128, 3><<<dim3(8, 12, 2), 512, SMEM128>>>(vh, vl, cdh, part, 1024, 1024, 512,
        vh + 1310720, vl + 1310720, fch,
        part + 1408 * 1024, 1024, CONV1D_SLICE, 11);
    finishrow2_k<<<1408, 256>>>(part, cdb, fcb, uh, ul, un, gph, gn);

    // att (+ gsraw folded as y=11,x=0): N=1280, K=1024, S=2 Ks=512 (222 active CTAs)
    gemm_sk<128, 3><<<dim3(10, 12, 2), 512, SMEM128>>>(uh, ul, wdh, part, 1280, 1024, 512,
        sth, stl, gph,
        part + GS_OFF, 128, 16384, 11);
    finish2_k<<<1696, 256>>>(part, att, gsraw);

    // fused sim + reductions
    sim_k<<<448, 192>>>(att, G, un, wmask, sall);
    scores_k<<<16, 256>>>(sall, sc, out);
    loss_k<<<1, 256>>>(sc, gsraw, sn, gn, out);
}